// round 9
// baseline (speedup 1.0000x reference)
#include <cuda_runtime.h>
#include <math.h>

// ---------------------------------------------------------------------------
// InteractionPredictor: e3nn-style equivariant GNN, fully fused fp32.
// R8: 4 edge-slots per lane (128 edges / 256-thread block, 8 warps x KC=8).
// "p-scheme" fold: p = cf*h per (u,j), weights FMA directly into output
// accumulators (no per-edge weight registers) -> weight-LDG per edge halves.
// Non-atomic slice reduction in 4-feature chunks (fits 48KB static smem).
// k_rec reduces via global float atomics into d_out (zeroed by k_lig).
// ---------------------------------------------------------------------------

#define TBE    256
#define EPB    128         /* edges per block         */
#define KC     8           /* k-chunk per warp        */
#define NW     8           /* warps per block         */
#define NF     40
#define NMAX   16384
#define EIMAX  65536

__device__ float g_node[NMAX * NF];
__device__ float g_msgs[NMAX * NF];
__device__ float g_lig [EIMAX * NF];

#define C24    0.20412414523193154f   /* sqrt(1/24)  */
#define C24S3  0.35355339059327373f   /* sqrt(1/8)   */
#define INVS3  0.57735026918962576f   /* 1/sqrt(3)   */
#define PWREC  0.05590169943749474f   /* 1/sqrt(320) */
#define DEMBC  8.4335731f             /* 1.14136*e^2 */
#define INV32  0.17677669529663687f   /* 1/sqrt(32)  */

__device__ __forceinline__ float siluN(float x) {
    return x * (1.0f / (1.0f + __expf(-x))) * 1.6789717f;
}

// ---------------------------------------------------------------------------
// node embedding; also zeroes the message accumulator for step 0
// ---------------------------------------------------------------------------
__global__ void k_embed(const float* __restrict__ x, int N, int A,
                        const float* __restrict__ W0, const float* __restrict__ W1) {
    int n = blockIdx.x * blockDim.x + threadIdx.x;
    if (n >= N) return;
    float inv = rsqrtf((float)A);
    float a[16];
#pragma unroll
    for (int b = 0; b < 16; b++) a[b] = (b < A) ? x[n * A + b] : 0.0f;
    float h[64];
#pragma unroll 4
    for (int k = 0; k < 64; k++) {
        float s = 0.0f;
#pragma unroll
        for (int b = 0; b < 16; b++)
            if (b < A) s += a[b] * W0[b * 64 + k];
        h[k] = siluN(s * inv) * 0.125f;
    }
    float* nr = g_node + n * NF;
#pragma unroll
    for (int w = 0; w < 16; w++) {
        float s = 0.0f;
#pragma unroll 8
        for (int k = 0; k < 64; k++) s += h[k] * W1[k * 16 + w];
        nr[w] = s;
    }
#pragma unroll
    for (int t = 0; t < 24; t++) nr[16 + t] = 0.0f;
    float* mr = g_msgs + n * NF;
#pragma unroll
    for (int t = 0; t < NF; t++) mr[t] = 0.0f;
}

// ---------------------------------------------------------------------------
// node update; re-zeroes this node's message row after consuming it
// ---------------------------------------------------------------------------
__global__ void k_update(int N, const float* __restrict__ imp, float degf,
                         const float* __restrict__ W0, const float* __restrict__ W1,
                         float gmul) {
    int n = blockIdx.x * blockDim.x + threadIdx.x;
    if (n >= N) return;
    float scale = imp[0] * rsqrtf(degf);
    float* nr = g_node + n * NF;
    float* mr = g_msgs + n * NF;
    float a[32];
#pragma unroll
    for (int t = 0; t < 16; t++) a[t] = mr[t] * scale;
#pragma unroll
    for (int t = 0; t < 16; t++) a[16 + t] = nr[t];
    float ge[24];
#pragma unroll
    for (int t = 0; t < 24; t++) ge[t] = (mr[16 + t] * scale + nr[16 + t]) * gmul;
#pragma unroll
    for (int t = 0; t < NF; t++) mr[t] = 0.0f;
    float h[64];
#pragma unroll 2
    for (int k = 0; k < 64; k++) {
        float s = 0.0f;
#pragma unroll
        for (int b = 0; b < 32; b++) s += a[b] * W0[b * 64 + k];
        h[k] = siluN(s * INV32) * 0.125f;
    }
    float sc[16];
#pragma unroll
    for (int w = 0; w < 16; w++) {
        float s = 0.0f;
#pragma unroll 8
        for (int k = 0; k < 64; k++) s += h[k] * W1[k * 16 + w];
        sc[w] = s;
    }
#pragma unroll
    for (int w = 0; w < 16; w++) nr[w] = sc[w];
#pragma unroll
    for (int t = 0; t < 24; t++) nr[16 + t] = ge[t];
}

// ---------------------------------------------------------------------------
__device__ __forceinline__ void demb_compute(float d, float* a) {
    float tt = d * 4.2f;
#pragma unroll
    for (int i = 0; i < 20; i++) {
        float diff = tt - (float)(i + 1);
        float p = diff + 1.0f, q = 1.0f - diff;
        float s1 = (p > 0.0f) ? __expf(-1.0f / p) : 0.0f;
        float s2 = (q > 0.0f) ? __expf(-1.0f / q) : 0.0f;
        a[i] = DEMBC * s1 * s2;
    }
}

// ===========================================================================
// Shared fold bodies (macros avoided; functions with slot arrays)
// shN layout: [f][EPB], shR layout: [3][EPB], shS: [warp][4][EPB]
// ===========================================================================

// scalar fold (blocks A+B) -> os[4][16]
__device__ __forceinline__ void fold_scalar4(
    const float h[4][KC], int lane,
    const float* __restrict__ shN, const float* __restrict__ shR,
    const float* __restrict__ W1k, float os[4][16])
{
#pragma unroll
    for (int s = 0; s < 4; s++)
#pragma unroll
        for (int t = 0; t < 16; t++) os[s][t] = 0.0f;

    // Block A: cols [u*16, +16), u<16 ; cf = C24 * xs_u
#pragma unroll 1
    for (int u = 0; u < 16; u++) {
        float cf[4];
#pragma unroll
        for (int s = 0; s < 4; s++) cf[s] = C24 * shN[u * EPB + lane + s * 32];
#pragma unroll
        for (int j = 0; j < KC; j++) {
            float p[4];
#pragma unroll
            for (int s = 0; s < 4; s++) p[s] = cf[s] * h[s][j];
            const float4* base = reinterpret_cast<const float4*>(W1k + j * 576 + u * 16);
#pragma unroll
            for (int qi = 0; qi < 4; qi++) {
                float4 q = __ldg(base + qi);
#pragma unroll
                for (int s = 0; s < 4; s++) {
                    os[s][qi*4+0] += p[s] * q.x;
                    os[s][qi*4+1] += p[s] * q.y;
                    os[s][qi*4+2] += p[s] * q.z;
                    os[s][qi*4+3] += p[s] * q.w;
                }
            }
        }
    }

    // Block B: cols [256+u*16), u<8 ; cf = C24 * (xv_u . r)
#pragma unroll 1
    for (int u = 0; u < 8; u++) {
        float cf[4];
#pragma unroll
        for (int s = 0; s < 4; s++) {
            int idx = lane + s * 32;
            cf[s] = C24 * (shN[(16 + u * 3) * EPB + idx] * shR[idx] +
                           shN[(17 + u * 3) * EPB + idx] * shR[EPB + idx] +
                           shN[(18 + u * 3) * EPB + idx] * shR[2 * EPB + idx]);
        }
#pragma unroll
        for (int j = 0; j < KC; j++) {
            float p[4];
#pragma unroll
            for (int s = 0; s < 4; s++) p[s] = cf[s] * h[s][j];
            const float4* base = reinterpret_cast<const float4*>(W1k + j * 576 + 256 + u * 16);
#pragma unroll
            for (int qi = 0; qi < 4; qi++) {
                float4 q = __ldg(base + qi);
#pragma unroll
                for (int s = 0; s < 4; s++) {
                    os[s][qi*4+0] += p[s] * q.x;
                    os[s][qi*4+1] += p[s] * q.y;
                    os[s][qi*4+2] += p[s] * q.z;
                    os[s][qi*4+3] += p[s] * q.w;
                }
            }
        }
    }
}

// vector fold, one half (t 0..3 or 4..7) -> ov[4][12]
__device__ __forceinline__ void fold_vector4(
    const float h[4][KC], int lane, int half,
    const float* __restrict__ shN,
    const float r0[4], const float r1[4], const float r2[4],
    const float* __restrict__ W1k, float ov[4][12])
{
#pragma unroll
    for (int s = 0; s < 4; s++)
#pragma unroll
        for (int t = 0; t < 12; t++) ov[s][t] = 0.0f;

    // Block C: cols [384 + u*8 + half*4), u<16 ; out gets * r_i
#pragma unroll 1
    for (int u = 0; u < 16; u++) {
        float cf[4];
#pragma unroll
        for (int s = 0; s < 4; s++) cf[s] = C24S3 * shN[u * EPB + lane + s * 32];
#pragma unroll
        for (int j = 0; j < KC; j++) {
            float4 q = __ldg(reinterpret_cast<const float4*>(W1k + j * 576 + 384 + u * 8 + half * 4));
            float qa[4] = {q.x, q.y, q.z, q.w};
            float p[4];
#pragma unroll
            for (int s = 0; s < 4; s++) p[s] = cf[s] * h[s][j];
#pragma unroll
            for (int t = 0; t < 4; t++) {
#pragma unroll
                for (int s = 0; s < 4; s++) {
                    float sv = p[s] * qa[t];
                    ov[s][t*3+0] += sv * r0[s];
                    ov[s][t*3+1] += sv * r1[s];
                    ov[s][t*3+2] += sv * r2[s];
                }
            }
        }
    }

    // Block D: cols [512 + u*8 + half*4), u<8 ; coef = C24 * xv_u[i]
#pragma unroll 1
    for (int u = 0; u < 8; u++) {
        float c0[4], c1[4], c2[4];
#pragma unroll
        for (int s = 0; s < 4; s++) {
            int idx = lane + s * 32;
            c0[s] = C24 * shN[(16 + u * 3) * EPB + idx];
            c1[s] = C24 * shN[(17 + u * 3) * EPB + idx];
            c2[s] = C24 * shN[(18 + u * 3) * EPB + idx];
        }
#pragma unroll
        for (int j = 0; j < KC; j++) {
            float4 q = __ldg(reinterpret_cast<const float4*>(W1k + j * 576 + 512 + u * 8 + half * 4));
            float qa[4] = {q.x, q.y, q.z, q.w};
#pragma unroll
            for (int t = 0; t < 4; t++) {
#pragma unroll
                for (int s = 0; s < 4; s++) {
                    float tv = h[s][j] * qa[t];
                    ov[s][t*3+0] += c0[s] * tv;
                    ov[s][t*3+1] += c1[s] * tv;
                    ov[s][t*3+2] += c2[s] * tv;
                }
            }
        }
    }
}

// ---------------------------------------------------------------------------
// message kernel: 128 edges / 256 threads, 8 warps x KC=8, 4 slots/lane
// ---------------------------------------------------------------------------
__global__ void __launch_bounds__(TBE, 2) k_msg(
    const float* __restrict__ pos,
    const int* __restrict__ srcI, const int* __restrict__ dstI,
    const float* __restrict__ eattr, int E, int B,
    const float* __restrict__ W0, const float* __restrict__ W1)
{
    __shared__ float shN[NF * EPB];        // 20 KB
    __shared__ float shS[NW * 4 * EPB];    // 16 KB (4-feature chunks)
    __shared__ float shR[3 * EPB];
    __shared__ int   shSi[EPB];
    __shared__ int   shDi[EPB];

    int tid  = threadIdx.x;
    int lane = tid & 31;
    int warp = tid >> 5;
    int e0 = blockIdx.x * EPB;

    if (tid < EPB) {
        int e = min(e0 + tid, E - 1);
        int si = srcI[e], di = dstI[e];
        shSi[tid] = si; shDi[tid] = di;
        float vx = pos[di * 3 + 0] - pos[si * 3 + 0];
        float vy = pos[di * 3 + 1] - pos[si * 3 + 1];
        float vz = pos[di * 3 + 2] - pos[si * 3 + 2];
        float rn = rsqrtf(vx * vx + vy * vy + vz * vz);
        shR[tid]           = vx * rn;
        shR[EPB + tid]     = vy * rn;
        shR[2 * EPB + tid] = vz * rn;
    }
    __syncthreads();

    for (int i = tid; i < NF * EPB; i += TBE) {
        int e = i & (EPB - 1), f = i >> 7;
        shN[f * EPB + e] = g_node[shSi[e] * NF + f];
    }

    float h[4][KC];
    {
        float inv = rsqrtf((float)B);
        int kb = warp * KC;
#pragma unroll
        for (int s = 0; s < 4; s++) {
            int e = min(e0 + lane + s * 32, E - 1);
            float aa[8];
#pragma unroll
            for (int b = 0; b < 8; b++) aa[b] = (b < B) ? eattr[e * B + b] : 0.0f;
#pragma unroll
            for (int j = 0; j < KC; j++) {
                float sm = 0.0f;
#pragma unroll
                for (int b = 0; b < 8; b++)
                    if (b < B) sm += aa[b] * W0[b * 64 + kb + j];
                h[s][j] = siluN(sm * inv) * 0.125f;
            }
        }
    }
    __syncthreads();

    const float* W1k = W1 + warp * KC * 576;

    // ---- scalar phase ----
    {
        float os[4][16];
        fold_scalar4(h, lane, shN, shR, W1k, os);
#pragma unroll 1
        for (int c = 0; c < 4; c++) {
            __syncthreads();
#pragma unroll
            for (int f = 0; f < 4; f++)
#pragma unroll
                for (int s = 0; s < 4; s++)
                    shS[warp * 4 * EPB + f * EPB + lane + s * 32] = os[s][c * 4 + f];
            __syncthreads();
            for (int i = tid; i < 4 * EPB; i += TBE) {
                float sm = 0.0f;
#pragma unroll
                for (int w = 0; w < NW; w++) sm += shS[w * 4 * EPB + i];
                int e = i & (EPB - 1), f = i >> 7;
                if (e0 + e < E) atomicAdd(&g_msgs[shDi[e] * NF + c * 4 + f], sm);
            }
        }
    }

    // ---- vector phases ----
    float r0[4], r1[4], r2[4];
#pragma unroll
    for (int s = 0; s < 4; s++) {
        int idx = lane + s * 32;
        r0[s] = shR[idx]; r1[s] = shR[EPB + idx]; r2[s] = shR[2 * EPB + idx];
    }
#pragma unroll 1
    for (int half = 0; half < 2; half++) {
        float ov[4][12];
        fold_vector4(h, lane, half, shN, r0, r1, r2, W1k, ov);
#pragma unroll 1
        for (int c = 0; c < 3; c++) {
            __syncthreads();
#pragma unroll
            for (int f = 0; f < 4; f++)
#pragma unroll
                for (int s = 0; s < 4; s++)
                    shS[warp * 4 * EPB + f * EPB + lane + s * 32] = ov[s][c * 4 + f];
            __syncthreads();
            for (int i = tid; i < 4 * EPB; i += TBE) {
                float sm = 0.0f;
#pragma unroll
                for (int w = 0; w < NW; w++) sm += shS[w * 4 * EPB + i];
                int e = i & (EPB - 1), f = i >> 7;
                if (e0 + e < E)
                    atomicAdd(&g_msgs[shDi[e] * NF + 16 + half * 12 + c * 4 + f], sm);
            }
        }
    }
}

// ---------------------------------------------------------------------------
// ligand embedding; also zeroes d_out for k_rec's atomic reduction
// ---------------------------------------------------------------------------
__global__ void __launch_bounds__(TBE, 2) k_lig(
    const float* __restrict__ pos,
    const int* __restrict__ recI, const int* __restrict__ ligI, int EI,
    const float* __restrict__ W0, const float* __restrict__ W1,
    float* __restrict__ out)
{
    __shared__ float shN[NF * EPB];
    __shared__ float shS[NW * 4 * EPB];
    __shared__ float shR[3 * EPB];
    __shared__ float shD[EPB];
    __shared__ int   shLi[EPB];

    int tid  = threadIdx.x;
    int lane = tid & 31;
    int warp = tid >> 5;
    int e0 = blockIdx.x * EPB;

    // zero d_out rows for this block's edges
    for (int i = tid; i < 8 * EPB; i += TBE) {
        int e = i >> 3;
        if (e0 + e < EI) out[(e0 + e) * 8 + (i & 7)] = 0.0f;
    }

    if (tid < EPB) {
        int e = min(e0 + tid, EI - 1);
        int ri = recI[e], li = ligI[e];
        shLi[tid] = li;
        float vx = pos[li * 3 + 0] - pos[ri * 3 + 0];
        float vy = pos[li * 3 + 1] - pos[ri * 3 + 1];
        float vz = pos[li * 3 + 2] - pos[ri * 3 + 2];
        float d2 = vx * vx + vy * vy + vz * vz;
        float invd = rsqrtf(d2);
        shR[tid]           = vx * invd;
        shR[EPB + tid]     = vy * invd;
        shR[2 * EPB + tid] = vz * invd;
        shD[tid]           = d2 * invd;
    }
    __syncthreads();

    for (int i = tid; i < NF * EPB; i += TBE) {
        int e = i & (EPB - 1), f = i >> 7;
        shN[f * EPB + e] = g_node[shLi[e] * NF + f];
    }

    float h[4][KC];
    {
        int kb = warp * KC;
#pragma unroll 1
        for (int s = 0; s < 4; s++) {
            float aa[20];
            demb_compute(shD[lane + s * 32], aa);
#pragma unroll
            for (int j = 0; j < KC; j++) {
                float sm = 0.0f;
#pragma unroll
                for (int i = 0; i < 20; i++) sm += aa[i] * W0[i * 64 + kb + j];
                h[s][j] = siluN(sm) * 0.125f;
            }
        }
    }
    __syncthreads();

    const float* W1k = W1 + warp * KC * 576;

    {
        float os[4][16];
        fold_scalar4(h, lane, shN, shR, W1k, os);
#pragma unroll 1
        for (int c = 0; c < 4; c++) {
            __syncthreads();
#pragma unroll
            for (int f = 0; f < 4; f++)
#pragma unroll
                for (int s = 0; s < 4; s++)
                    shS[warp * 4 * EPB + f * EPB + lane + s * 32] = os[s][c * 4 + f];
            __syncthreads();
            for (int i = tid; i < 4 * EPB; i += TBE) {
                float sm = 0.0f;
#pragma unroll
                for (int w = 0; w < NW; w++) sm += shS[w * 4 * EPB + i];
                int e = i & (EPB - 1), f = i >> 7;
                if (e0 + e < EI) g_lig[(e0 + e) * NF + c * 4 + f] = sm;
            }
        }
    }

    float r0[4], r1[4], r2[4];
#pragma unroll
    for (int s = 0; s < 4; s++) {
        int idx = lane + s * 32;
        r0[s] = shR[idx]; r1[s] = shR[EPB + idx]; r2[s] = shR[2 * EPB + idx];
    }
#pragma unroll 1
    for (int half = 0; half < 2; half++) {
        float ov[4][12];
        fold_vector4(h, lane, half, shN, r0, r1, r2, W1k, ov);
#pragma unroll 1
        for (int c = 0; c < 3; c++) {
            __syncthreads();
#pragma unroll
            for (int f = 0; f < 4; f++)
#pragma unroll
                for (int s = 0; s < 4; s++)
                    shS[warp * 4 * EPB + f * EPB + lane + s * 32] = ov[s][c * 4 + f];
            __syncthreads();
            for (int i = tid; i < 4 * EPB; i += TBE) {
                float sm = 0.0f;
#pragma unroll
                for (int w = 0; w < NW; w++) sm += shS[w * 4 * EPB + i];
                int e = i & (EPB - 1), f = i >> 7;
                if (e0 + e < EI)
                    g_lig[(e0 + e) * NF + 16 + half * 12 + c * 4 + f] = sm;
            }
        }
    }
}

// ---------------------------------------------------------------------------
// receptor TP readout: 128 edges / block, 4 slots/lane, k-split 8 warps;
// partials reduced via global atomics into pre-zeroed d_out.
// ---------------------------------------------------------------------------
__global__ void __launch_bounds__(TBE, 2) k_rec(
    const float* __restrict__ pos,
    const int* __restrict__ recI, const int* __restrict__ ligI, int EI,
    const float* __restrict__ W0, const float* __restrict__ W1,
    float* __restrict__ out)
{
    __shared__ float shL [NF * EPB];   // 20 KB
    __shared__ float shRn[NF * EPB];   // 20 KB
    __shared__ float shD [EPB];
    __shared__ int   shRi[EPB];

    int tid  = threadIdx.x;
    int lane = tid & 31;
    int warp = tid >> 5;
    int e0 = blockIdx.x * EPB;

    if (tid < EPB) {
        int e = min(e0 + tid, EI - 1);
        int ri = recI[e], li = ligI[e];
        shRi[tid] = ri;
        float vx = pos[li * 3 + 0] - pos[ri * 3 + 0];
        float vy = pos[li * 3 + 1] - pos[ri * 3 + 1];
        float vz = pos[li * 3 + 2] - pos[ri * 3 + 2];
        float d2 = vx * vx + vy * vy + vz * vz;
        shD[tid] = d2 * rsqrtf(d2);
    }
    __syncthreads();

    for (int i = tid; i < NF * EPB; i += TBE) {
        int e = i & (EPB - 1), f = i >> 7;
        int ec = min(e0 + e, EI - 1);
        shL [f * EPB + e] = g_lig[ec * NF + f];
        shRn[f * EPB + e] = g_node[shRi[e] * NF + f];
    }

    float h[4][KC];
    {
        int kb = warp * KC;
#pragma unroll 1
        for (int s = 0; s < 4; s++) {
            float aa[20];
            demb_compute(shD[lane + s * 32], aa);
#pragma unroll
            for (int j = 0; j < KC; j++) {
                float sm = 0.0f;
#pragma unroll
                for (int i = 0; i < 20; i++) sm += aa[i] * W0[i * 64 + kb + j];
                h[s][j] = siluN(sm) * 0.125f;
            }
        }
    }
    __syncthreads();

    float acc[4][8];
#pragma unroll
    for (int s = 0; s < 4; s++)
#pragma unroll
        for (int t = 0; t < 8; t++) acc[s][t] = 0.0f;
    const float* Wk = W1 + warp * KC * 2560;

    // scalar x scalar -> 8x0e : w1[u][v][o] at (u*16+v)*8
#pragma unroll 1
    for (int u = 0; u < 16; u++) {
        float lu[4];
#pragma unroll
        for (int s = 0; s < 4; s++) lu[s] = shL[u * EPB + lane + s * 32];
#pragma unroll 1
        for (int v = 0; v < 16; v++) {
            float cf[4];
#pragma unroll
            for (int s = 0; s < 4; s++) cf[s] = lu[s] * shRn[v * EPB + lane + s * 32];
            const float* base = Wk + (u * 16 + v) * 8;
#pragma unroll
            for (int j = 0; j < KC; j++) {
                float p[4];
#pragma unroll
                for (int s = 0; s < 4; s++) p[s] = cf[s] * h[s][j];
                const float4* bp = reinterpret_cast<const float4*>(base + j * 2560);
                float4 q0 = __ldg(bp), q1 = __ldg(bp + 1);
#pragma unroll
                for (int s = 0; s < 4; s++) {
                    acc[s][0] += p[s] * q0.x; acc[s][1] += p[s] * q0.y;
                    acc[s][2] += p[s] * q0.z; acc[s][3] += p[s] * q0.w;
                    acc[s][4] += p[s] * q1.x; acc[s][5] += p[s] * q1.y;
                    acc[s][6] += p[s] * q1.z; acc[s][7] += p[s] * q1.w;
                }
            }
        }
    }

    // vector x vector -> 8x0e : w2 at 2048 + (u*8+v)*8, coef (lv.rv)/sqrt3
#pragma unroll 1
    for (int u = 0; u < 8; u++) {
        float la0[4], la1[4], la2[4];
#pragma unroll
        for (int s = 0; s < 4; s++) {
            int idx = lane + s * 32;
            la0[s] = shL[(16 + u * 3) * EPB + idx];
            la1[s] = shL[(17 + u * 3) * EPB + idx];
            la2[s] = shL[(18 + u * 3) * EPB + idx];
        }
#pragma unroll 1
        for (int v = 0; v < 8; v++) {
            float cf[4];
#pragma unroll
            for (int s = 0; s < 4; s++) {
                int idx = lane + s * 32;
                cf[s] = (la0[s] * shRn[(16 + v * 3) * EPB + idx] +
                         la1[s] * shRn[(17 + v * 3) * EPB + idx] +
                         la2[s] * shRn[(18 + v * 3) * EPB + idx]) * INVS3;
            }
            const float* base = Wk + 2048 + (u * 8 + v) * 8;
#pragma unroll
            for (int j = 0; j < KC; j++) {
                float p[4];
#pragma unroll
                for (int s = 0; s < 4; s++) p[s] = cf[s] * h[s][j];
                const float4* bp = reinterpret_cast<const float4*>(base + j * 2560);
                float4 q0 = __ldg(bp), q1 = __ldg(bp + 1);
#pragma unroll
                for (int s = 0; s < 4; s++) {
                    acc[s][0] += p[s] * q0.x; acc[s][1] += p[s] * q0.y;
                    acc[s][2] += p[s] * q0.z; acc[s][3] += p[s] * q0.w;
                    acc[s][4] += p[s] * q1.x; acc[s][5] += p[s] * q1.y;
                    acc[s][6] += p[s] * q1.z; acc[s][7] += p[s] * q1.w;
                }
            }
        }
    }

    // reduce this warp's partials into (pre-zeroed) output
#pragma unroll
    for (int s = 0; s < 4; s++) {
        int e = e0 + lane + s * 32;
        if (e < EI) {
#pragma unroll
            for (int t = 0; t < 8; t++)
                atomicAdd(&out[e * 8 + t], PWREC * acc[s][t]);
        }
    }
}

// ---------------------------------------------------------------------------
// host launcher (graph-capturable: kernel launches only)
// ---------------------------------------------------------------------------
extern "C" void kernel_launch(void* const* d_in, const int* in_sizes, int n_in,
                              void* d_out, int out_size) {
    (void)n_in; (void)out_size;
    const float* x       = (const float*)d_in[0];
    const float* pos     = (const float*)d_in[1];
    const int*   eidx    = (const int*)  d_in[2];
    const float* eattr   = (const float*)d_in[3];
    const int*   iidx    = (const int*)  d_in[4];
    const float* emb_w0  = (const float*)d_in[5];
    const float* emb_w1  = (const float*)d_in[6];
    const float* imp0    = (const float*)d_in[7];
    const float* msg0_w0 = (const float*)d_in[8];
    const float* msg0_w1 = (const float*)d_in[9];
    const float* upd0_w0 = (const float*)d_in[10];
    const float* upd0_w1 = (const float*)d_in[11];
    const float* imp1    = (const float*)d_in[12];
    const float* msg1_w0 = (const float*)d_in[13];
    const float* msg1_w1 = (const float*)d_in[14];
    const float* upd1_w0 = (const float*)d_in[15];
    const float* upd1_w1 = (const float*)d_in[16];
    const float* lig_w0  = (const float*)d_in[17];
    const float* lig_w1  = (const float*)d_in[18];
    const float* rec_w0  = (const float*)d_in[19];
    const float* rec_w1  = (const float*)d_in[20];

    int N  = in_sizes[1] / 3;
    int A  = in_sizes[0] / N;
    int E  = in_sizes[2] / 2;
    int B  = in_sizes[3] / E;
    int EI = in_sizes[4] / 2;
    const int* src  = eidx;
    const int* dst  = eidx + E;
    const int* recI = iidx;
    const int* ligI = iidx + EI;
    float degf = (float)E / (float)N;

    int gn = (N + 127) / 128;
    int ge = (E + EPB - 1) / EPB;
    int gi = (EI + EPB - 1) / EPB;

    k_embed<<<gn, 128>>>(x, N, A, emb_w0, emb_w1);      // also zeroes g_msgs

    k_msg<<<ge, TBE>>>(pos, src, dst, eattr, E, B, msg0_w0, msg0_w1);
    k_update<<<gn, 128>>>(N, imp0, degf, upd0_w0, upd0_w1, 1.0f);  // re-zeroes g_msgs

    k_msg<<<ge, TBE>>>(pos, src, dst, eattr, E, B, msg1_w0, msg1_w1);
    k_update<<<gn, 128>>>(N, imp1, degf, upd1_w0, upd1_w1, 0.5f);

    k_lig<<<gi, TBE>>>(pos, recI, ligI, EI, lig_w0, lig_w1, (float*)d_out);  // zeroes d_out
    k_rec<<<gi, TBE>>>(pos, recI, ligI, EI, rec_w0, rec_w1, (float*)d_out);
}

// round 10
// speedup vs baseline: 1.6723x; 1.6723x over previous
#include <cuda_runtime.h>
#include <math.h>

// ---------------------------------------------------------------------------
// InteractionPredictor: e3nn-style equivariant GNN, fully fused fp32.
// R9 = R7 (known-good) k_msg/k_lig [64 edges/256 thr, 8 warps x KC=8,
// 2 edge-slots/lane, non-atomic slice reduction] + R8-style k_rec
// [128 edges/block, 4 edge-slots/lane -> weight-LDG per edge halved,
// small acc set so no spills; global atomic reduction into d_out].
// ---------------------------------------------------------------------------

#define TBE    256         /* threads per edge block      */
#define EPB    64          /* edges per block (msg/lig)   */
#define EPR    128         /* edges per block (rec)       */
#define KC     8           /* k-chunk per warp (8 warps)  */
#define NW     8           /* warps per block             */
#define NF     40
#define NMAX   16384
#define EIMAX  65536

__device__ float g_node[NMAX * NF];
__device__ float g_msgs[NMAX * NF];
__device__ float g_lig [EIMAX * NF];

#define C24    0.20412414523193154f   /* sqrt(1/24)  */
#define C24S3  0.35355339059327373f   /* sqrt(1/8)   */
#define INVS3  0.57735026918962576f   /* 1/sqrt(3)   */
#define PWREC  0.05590169943749474f   /* 1/sqrt(320) */
#define DEMBC  8.4335731f             /* 1.14136*e^2 */
#define INV32  0.17677669529663687f   /* 1/sqrt(32)  */

__device__ __forceinline__ float siluN(float x) {
    return x * (1.0f / (1.0f + __expf(-x))) * 1.6789717f;
}

// ---------------------------------------------------------------------------
// node embedding; also zeroes the message accumulator for step 0
// ---------------------------------------------------------------------------
__global__ void k_embed(const float* __restrict__ x, int N, int A,
                        const float* __restrict__ W0, const float* __restrict__ W1) {
    int n = blockIdx.x * blockDim.x + threadIdx.x;
    if (n >= N) return;
    float inv = rsqrtf((float)A);
    float a[16];
#pragma unroll
    for (int b = 0; b < 16; b++) a[b] = (b < A) ? x[n * A + b] : 0.0f;
    float h[64];
#pragma unroll 4
    for (int k = 0; k < 64; k++) {
        float s = 0.0f;
#pragma unroll
        for (int b = 0; b < 16; b++)
            if (b < A) s += a[b] * W0[b * 64 + k];
        h[k] = siluN(s * inv) * 0.125f;
    }
    float* nr = g_node + n * NF;
#pragma unroll
    for (int w = 0; w < 16; w++) {
        float s = 0.0f;
#pragma unroll 8
        for (int k = 0; k < 64; k++) s += h[k] * W1[k * 16 + w];
        nr[w] = s;
    }
#pragma unroll
    for (int t = 0; t < 24; t++) nr[16 + t] = 0.0f;
    float* mr = g_msgs + n * NF;
#pragma unroll
    for (int t = 0; t < NF; t++) mr[t] = 0.0f;
}

// ---------------------------------------------------------------------------
// node update; re-zeroes this node's message row after consuming it
// ---------------------------------------------------------------------------
__global__ void k_update(int N, const float* __restrict__ imp, float degf,
                         const float* __restrict__ W0, const float* __restrict__ W1,
                         float gmul) {
    int n = blockIdx.x * blockDim.x + threadIdx.x;
    if (n >= N) return;
    float scale = imp[0] * rsqrtf(degf);
    float* nr = g_node + n * NF;
    float* mr = g_msgs + n * NF;
    float a[32];
#pragma unroll
    for (int t = 0; t < 16; t++) a[t] = mr[t] * scale;
#pragma unroll
    for (int t = 0; t < 16; t++) a[16 + t] = nr[t];
    float ge[24];
#pragma unroll
    for (int t = 0; t < 24; t++) ge[t] = (mr[16 + t] * scale + nr[16 + t]) * gmul;
#pragma unroll
    for (int t = 0; t < NF; t++) mr[t] = 0.0f;
    float h[64];
#pragma unroll 2
    for (int k = 0; k < 64; k++) {
        float s = 0.0f;
#pragma unroll
        for (int b = 0; b < 32; b++) s += a[b] * W0[b * 64 + k];
        h[k] = siluN(s * INV32) * 0.125f;
    }
    float sc[16];
#pragma unroll
    for (int w = 0; w < 16; w++) {
        float s = 0.0f;
#pragma unroll 8
        for (int k = 0; k < 64; k++) s += h[k] * W1[k * 16 + w];
        sc[w] = s;
    }
#pragma unroll
    for (int w = 0; w < 16; w++) nr[w] = sc[w];
#pragma unroll
    for (int t = 0; t < 24; t++) nr[16 + t] = ge[t];
}

// ---------------------------------------------------------------------------
__device__ __forceinline__ void demb_compute(float d, float* a) {
    float tt = d * 4.2f;
#pragma unroll
    for (int i = 0; i < 20; i++) {
        float diff = tt - (float)(i + 1);
        float p = diff + 1.0f, q = 1.0f - diff;
        float s1 = (p > 0.0f) ? __expf(-1.0f / p) : 0.0f;
        float s2 = (q > 0.0f) ? __expf(-1.0f / q) : 0.0f;
        a[i] = DEMBC * s1 * s2;
    }
}

// ---------------------------------------------------------------------------
// Scalar-output fold (blocks A+B -> 16 features); writes this warp's slice.
// (2 edge-slots per lane; EPB=64)
// ---------------------------------------------------------------------------
__device__ __forceinline__ void fold_scalar(
    const float* __restrict__ ha, const float* __restrict__ hb, int lane,
    const float* __restrict__ shN, const float* __restrict__ shR,
    const float* __restrict__ W1k, float* __restrict__ slice)
{
    float ra0 = shR[lane],      ra1 = shR[EPB + lane],      ra2 = shR[2 * EPB + lane];
    float rb0 = shR[lane + 32], rb1 = shR[EPB + lane + 32], rb2 = shR[2 * EPB + lane + 32];

    float osA[16], osB[16];
#pragma unroll
    for (int t = 0; t < 16; t++) { osA[t] = 0.0f; osB[t] = 0.0f; }

    // Block A: 0e x 0e -> 0e ; cols [u*16, +16), u<16
#pragma unroll 1
    for (int u = 0; u < 16; u++) {
        float wa[16], wb[16];
#pragma unroll
        for (int t = 0; t < 16; t++) { wa[t] = 0.0f; wb[t] = 0.0f; }
        const float* base = W1k + u * 16;
#pragma unroll
        for (int j = 0; j < KC; j++) {
            const float4* p = reinterpret_cast<const float4*>(base + j * 576);
            float4 q0 = __ldg(p), q1 = __ldg(p + 1), q2 = __ldg(p + 2), q3 = __ldg(p + 3);
            float A = ha[j], Bv = hb[j];
            wa[0]+=A*q0.x; wa[1]+=A*q0.y; wa[2]+=A*q0.z; wa[3]+=A*q0.w;
            wa[4]+=A*q1.x; wa[5]+=A*q1.y; wa[6]+=A*q1.z; wa[7]+=A*q1.w;
            wa[8]+=A*q2.x; wa[9]+=A*q2.y; wa[10]+=A*q2.z; wa[11]+=A*q2.w;
            wa[12]+=A*q3.x; wa[13]+=A*q3.y; wa[14]+=A*q3.z; wa[15]+=A*q3.w;
            wb[0]+=Bv*q0.x; wb[1]+=Bv*q0.y; wb[2]+=Bv*q0.z; wb[3]+=Bv*q0.w;
            wb[4]+=Bv*q1.x; wb[5]+=Bv*q1.y; wb[6]+=Bv*q1.z; wb[7]+=Bv*q1.w;
            wb[8]+=Bv*q2.x; wb[9]+=Bv*q2.y; wb[10]+=Bv*q2.z; wb[11]+=Bv*q2.w;
            wb[12]+=Bv*q3.x; wb[13]+=Bv*q3.y; wb[14]+=Bv*q3.z; wb[15]+=Bv*q3.w;
        }
        float cfa = C24 * shN[u * EPB + lane];
        float cfb = C24 * shN[u * EPB + lane + 32];
#pragma unroll
        for (int t = 0; t < 16; t++) { osA[t] += cfa * wa[t]; osB[t] += cfb * wb[t]; }
    }

    // Block B: 1o x 1o -> 0e ; cols [256+u*16), u<8 ; coef C24*(xv_u . r)
#pragma unroll 1
    for (int u = 0; u < 8; u++) {
        float wa[16], wb[16];
#pragma unroll
        for (int t = 0; t < 16; t++) { wa[t] = 0.0f; wb[t] = 0.0f; }
        const float* base = W1k + 256 + u * 16;
#pragma unroll
        for (int j = 0; j < KC; j++) {
            const float4* p = reinterpret_cast<const float4*>(base + j * 576);
            float4 q0 = __ldg(p), q1 = __ldg(p + 1), q2 = __ldg(p + 2), q3 = __ldg(p + 3);
            float A = ha[j], Bv = hb[j];
            wa[0]+=A*q0.x; wa[1]+=A*q0.y; wa[2]+=A*q0.z; wa[3]+=A*q0.w;
            wa[4]+=A*q1.x; wa[5]+=A*q1.y; wa[6]+=A*q1.z; wa[7]+=A*q1.w;
            wa[8]+=A*q2.x; wa[9]+=A*q2.y; wa[10]+=A*q2.z; wa[11]+=A*q2.w;
            wa[12]+=A*q3.x; wa[13]+=A*q3.y; wa[14]+=A*q3.z; wa[15]+=A*q3.w;
            wb[0]+=Bv*q0.x; wb[1]+=Bv*q0.y; wb[2]+=Bv*q0.z; wb[3]+=Bv*q0.w;
            wb[4]+=Bv*q1.x; wb[5]+=Bv*q1.y; wb[6]+=Bv*q1.z; wb[7]+=Bv*q1.w;
            wb[8]+=Bv*q2.x; wb[9]+=Bv*q2.y; wb[10]+=Bv*q2.z; wb[11]+=Bv*q2.w;
            wb[12]+=Bv*q3.x; wb[13]+=Bv*q3.y; wb[14]+=Bv*q3.z; wb[15]+=Bv*q3.w;
        }
        float cfa = C24 * (shN[(16 + u * 3) * EPB + lane] * ra0 +
                           shN[(17 + u * 3) * EPB + lane] * ra1 +
                           shN[(18 + u * 3) * EPB + lane] * ra2);
        float cfb = C24 * (shN[(16 + u * 3) * EPB + lane + 32] * rb0 +
                           shN[(17 + u * 3) * EPB + lane + 32] * rb1 +
                           shN[(18 + u * 3) * EPB + lane + 32] * rb2);
#pragma unroll
        for (int t = 0; t < 16; t++) { osA[t] += cfa * wa[t]; osB[t] += cfb * wb[t]; }
    }

#pragma unroll
    for (int t = 0; t < 16; t++) {
        slice[t * EPB + lane]      = osA[t];
        slice[t * EPB + lane + 32] = osB[t];
    }
}

// ---------------------------------------------------------------------------
// Vector-output fold, one half (4 of the 8 vector mults -> 12 features).
// ---------------------------------------------------------------------------
__device__ __forceinline__ void fold_vector_half(
    const float* __restrict__ ha, const float* __restrict__ hb, int lane,
    const float* __restrict__ shN, const float* __restrict__ shR, int half,
    const float* __restrict__ W1k, float* __restrict__ slice)
{
    float ra0 = shR[lane],      ra1 = shR[EPB + lane],      ra2 = shR[2 * EPB + lane];
    float rb0 = shR[lane + 32], rb1 = shR[EPB + lane + 32], rb2 = shR[2 * EPB + lane + 32];

    float ovA[12], ovB[12];
#pragma unroll
    for (int t = 0; t < 12; t++) { ovA[t] = 0.0f; ovB[t] = 0.0f; }

    // Block C: 0e x 1o -> 1o ; cols [384 + u*8 + half*4), u<16
#pragma unroll 1
    for (int u = 0; u < 16; u++) {
        float wa[4], wb[4];
#pragma unroll
        for (int t = 0; t < 4; t++) { wa[t] = 0.0f; wb[t] = 0.0f; }
        const float* base = W1k + 384 + u * 8 + half * 4;
#pragma unroll
        for (int j = 0; j < KC; j++) {
            float4 q = __ldg(reinterpret_cast<const float4*>(base + j * 576));
            float A = ha[j], Bv = hb[j];
            wa[0]+=A*q.x; wa[1]+=A*q.y; wa[2]+=A*q.z; wa[3]+=A*q.w;
            wb[0]+=Bv*q.x; wb[1]+=Bv*q.y; wb[2]+=Bv*q.z; wb[3]+=Bv*q.w;
        }
        float cfa = C24S3 * shN[u * EPB + lane];
        float cfb = C24S3 * shN[u * EPB + lane + 32];
#pragma unroll
        for (int t = 0; t < 4; t++) {
            float sa = cfa * wa[t], sb = cfb * wb[t];
            ovA[t*3+0] += sa * ra0; ovA[t*3+1] += sa * ra1; ovA[t*3+2] += sa * ra2;
            ovB[t*3+0] += sb * rb0; ovB[t*3+1] += sb * rb1; ovB[t*3+2] += sb * rb2;
        }
    }

    // Block D: 1o x 0e -> 1o ; cols [512 + u*8 + half*4), u<8
#pragma unroll 1
    for (int u = 0; u < 8; u++) {
        float wa[4], wb[4];
#pragma unroll
        for (int t = 0; t < 4; t++) { wa[t] = 0.0f; wb[t] = 0.0f; }
        const float* base = W1k + 512 + u * 8 + half * 4;
#pragma unroll
        for (int j = 0; j < KC; j++) {
            float4 q = __ldg(reinterpret_cast<const float4*>(base + j * 576));
            float A = ha[j], Bv = hb[j];
            wa[0]+=A*q.x; wa[1]+=A*q.y; wa[2]+=A*q.z; wa[3]+=A*q.w;
            wb[0]+=Bv*q.x; wb[1]+=Bv*q.y; wb[2]+=Bv*q.z; wb[3]+=Bv*q.w;
        }
        float ca0 = C24 * shN[(16 + u * 3) * EPB + lane];
        float ca1 = C24 * shN[(17 + u * 3) * EPB + lane];
        float ca2 = C24 * shN[(18 + u * 3) * EPB + lane];
        float cb0 = C24 * shN[(16 + u * 3) * EPB + lane + 32];
        float cb1 = C24 * shN[(17 + u * 3) * EPB + lane + 32];
        float cb2 = C24 * shN[(18 + u * 3) * EPB + lane + 32];
#pragma unroll
        for (int t = 0; t < 4; t++) {
            ovA[t*3+0] += ca0 * wa[t]; ovA[t*3+1] += ca1 * wa[t]; ovA[t*3+2] += ca2 * wa[t];
            ovB[t*3+0] += cb0 * wb[t]; ovB[t*3+1] += cb1 * wb[t]; ovB[t*3+2] += cb2 * wb[t];
        }
    }

#pragma unroll
    for (int t = 0; t < 12; t++) {
        slice[t * EPB + lane]      = ovA[t];
        slice[t * EPB + lane + 32] = ovB[t];
    }
}

// ---------------------------------------------------------------------------
// message kernel: 64 edges / 256 threads, 8 warps x KC=8, slice reduction
// ---------------------------------------------------------------------------
__global__ void __launch_bounds__(TBE, 2) k_msg(
    const float* __restrict__ pos,
    const int* __restrict__ srcI, const int* __restrict__ dstI,
    const float* __restrict__ eattr, int E, int B,
    const float* __restrict__ W0, const float* __restrict__ W1)
{
    __shared__ float shN[NF * EPB];          // 10 KB
    __shared__ float shS[NW * 16 * EPB];     // 32 KB
    __shared__ float shR[3 * EPB];
    __shared__ int   shSi[EPB];
    __shared__ int   shDi[EPB];

    int tid  = threadIdx.x;
    int lane = tid & 31;
    int warp = tid >> 5;
    int e0 = blockIdx.x * EPB;

    if (tid < EPB) {
        int e = min(e0 + tid, E - 1);
        int si = srcI[e], di = dstI[e];
        shSi[tid] = si; shDi[tid] = di;
        float vx = pos[di * 3 + 0] - pos[si * 3 + 0];
        float vy = pos[di * 3 + 1] - pos[si * 3 + 1];
        float vz = pos[di * 3 + 2] - pos[si * 3 + 2];
        float rn = rsqrtf(vx * vx + vy * vy + vz * vz);
        shR[tid]           = vx * rn;
        shR[EPB + tid]     = vy * rn;
        shR[2 * EPB + tid] = vz * rn;
    }
    __syncthreads();

    for (int i = tid; i < NF * EPB; i += TBE) {
        int e = i & (EPB - 1), f = i >> 6;
        shN[f * EPB + e] = g_node[shSi[e] * NF + f];
    }

    float ha[KC], hb[KC];
    {
        float inv = rsqrtf((float)B);
        int kb = warp * KC;
        int ea = min(e0 + lane, E - 1);
        int eb = min(e0 + lane + 32, E - 1);
        float aa[8], ab[8];
#pragma unroll
        for (int b = 0; b < 8; b++) {
            aa[b] = (b < B) ? eattr[ea * B + b] : 0.0f;
            ab[b] = (b < B) ? eattr[eb * B + b] : 0.0f;
        }
#pragma unroll
        for (int j = 0; j < KC; j++) {
            float sa = 0.0f, sb = 0.0f;
#pragma unroll
            for (int b = 0; b < 8; b++)
                if (b < B) {
                    float w = W0[b * 64 + kb + j];
                    sa += aa[b] * w; sb += ab[b] * w;
                }
            ha[j] = siluN(sa * inv) * 0.125f;
            hb[j] = siluN(sb * inv) * 0.125f;
        }
    }
    __syncthreads();

    const float* W1k = W1 + warp * KC * 576;

    // ---- scalar phase ----
    fold_scalar(ha, hb, lane, shN, shR, W1k, shS + warp * 16 * EPB);
    __syncthreads();
    for (int i = tid; i < 16 * EPB; i += TBE) {
        float s = 0.0f;
#pragma unroll
        for (int w = 0; w < NW; w++) s += shS[w * 16 * EPB + i];
        int e = i & (EPB - 1), f = i >> 6;
        if (e0 + e < E) atomicAdd(&g_msgs[shDi[e] * NF + f], s);
    }
    __syncthreads();

    // ---- vector phases (2 halves of 12 features) ----
#pragma unroll 1
    for (int half = 0; half < 2; half++) {
        fold_vector_half(ha, hb, lane, shN, shR, half, W1k, shS + warp * 12 * EPB);
        __syncthreads();
        for (int i = tid; i < 12 * EPB; i += TBE) {
            float s = 0.0f;
#pragma unroll
            for (int w = 0; w < NW; w++) s += shS[w * 12 * EPB + i];
            int e = i & (EPB - 1), f = i >> 6;
            if (e0 + e < E) atomicAdd(&g_msgs[shDi[e] * NF + 16 + half * 12 + f], s);
        }
        __syncthreads();
    }
}

// ---------------------------------------------------------------------------
// ligand embedding; also zeroes d_out rows for k_rec's atomic reduction
// ---------------------------------------------------------------------------
__global__ void __launch_bounds__(TBE, 2) k_lig(
    const float* __restrict__ pos,
    const int* __restrict__ recI, const int* __restrict__ ligI, int EI,
    const float* __restrict__ W0, const float* __restrict__ W1,
    float* __restrict__ out)
{
    __shared__ float shN[NF * EPB];
    __shared__ float shS[NW * 16 * EPB];
    __shared__ float shR[3 * EPB];
    __shared__ float shD[EPB];
    __shared__ int   shLi[EPB];

    int tid  = threadIdx.x;
    int lane = tid & 31;
    int warp = tid >> 5;
    int e0 = blockIdx.x * EPB;

    // zero this block's output rows (k_rec accumulates atomically)
    for (int i = tid; i < 8 * EPB; i += TBE) {
        int e = i >> 3;
        if (e0 + e < EI) out[(e0 + e) * 8 + (i & 7)] = 0.0f;
    }

    if (tid < EPB) {
        int e = min(e0 + tid, EI - 1);
        int ri = recI[e], li = ligI[e];
        shLi[tid] = li;
        float vx = pos[li * 3 + 0] - pos[ri * 3 + 0];
        float vy = pos[li * 3 + 1] - pos[ri * 3 + 1];
        float vz = pos[li * 3 + 2] - pos[ri * 3 + 2];
        float d2 = vx * vx + vy * vy + vz * vz;
        float invd = rsqrtf(d2);
        shR[tid]           = vx * invd;
        shR[EPB + tid]     = vy * invd;
        shR[2 * EPB + tid] = vz * invd;
        shD[tid]           = d2 * invd;
    }
    __syncthreads();

    for (int i = tid; i < NF * EPB; i += TBE) {
        int e = i & (EPB - 1), f = i >> 6;
        shN[f * EPB + e] = g_node[shLi[e] * NF + f];
    }

    float ha[KC], hb[KC];
    {
        int kb = warp * KC;
        float aa[20], ab[20];
        demb_compute(shD[lane],      aa);
        demb_compute(shD[lane + 32], ab);
#pragma unroll
        for (int j = 0; j < KC; j++) {
            float sa = 0.0f, sb = 0.0f;
#pragma unroll
            for (int i = 0; i < 20; i++) {
                float w = W0[i * 64 + kb + j];
                sa += aa[i] * w; sb += ab[i] * w;
            }
            ha[j] = siluN(sa) * 0.125f;
            hb[j] = siluN(sb) * 0.125f;
        }
    }
    __syncthreads();

    const float* W1k = W1 + warp * KC * 576;

    fold_scalar(ha, hb, lane, shN, shR, W1k, shS + warp * 16 * EPB);
    __syncthreads();
    for (int i = tid; i < 16 * EPB; i += TBE) {
        float s = 0.0f;
#pragma unroll
        for (int w = 0; w < NW; w++) s += shS[w * 16 * EPB + i];
        int e = i & (EPB - 1), f = i >> 6;
        if (e0 + e < EI) g_lig[(e0 + e) * NF + f] = s;
    }
    __syncthreads();

#pragma unroll 1
    for (int half = 0; half < 2; half++) {
        fold_vector_half(ha, hb, lane, shN, shR, half, W1k, shS + warp * 12 * EPB);
        __syncthreads();
        for (int i = tid; i < 12 * EPB; i += TBE) {
            float s = 0.0f;
#pragma unroll
            for (int w = 0; w < NW; w++) s += shS[w * 12 * EPB + i];
            int e = i & (EPB - 1), f = i >> 6;
            if (e0 + e < EI) g_lig[(e0 + e) * NF + 16 + half * 12 + f] = s;
        }
        __syncthreads();
    }
}

// ---------------------------------------------------------------------------
// receptor TP readout: 128 edges / block, 4 edge-slots/lane, 8 warps split k;
// partials reduced via global atomics into d_out (pre-zeroed by k_lig).
// ---------------------------------------------------------------------------
__global__ void __launch_bounds__(TBE, 2) k_rec(
    const float* __restrict__ pos,
    const int* __restrict__ recI, const int* __restrict__ ligI, int EI,
    const float* __restrict__ W0, const float* __restrict__ W1,
    float* __restrict__ out)
{
    __shared__ float shL [NF * EPR];   // 20 KB
    __shared__ float shRn[NF * EPR];   // 20 KB
    __shared__ float shD [EPR];
    __shared__ int   shRi[EPR];

    int tid  = threadIdx.x;
    int lane = tid & 31;
    int warp = tid >> 5;
    int e0 = blockIdx.x * EPR;

    if (tid < EPR) {
        int e = min(e0 + tid, EI - 1);
        int ri = recI[e], li = ligI[e];
        shRi[tid] = ri;
        float vx = pos[li * 3 + 0] - pos[ri * 3 + 0];
        float vy = pos[li * 3 + 1] - pos[ri * 3 + 1];
        float vz = pos[li * 3 + 2] - pos[ri * 3 + 2];
        float d2 = vx * vx + vy * vy + vz * vz;
        shD[tid] = d2 * rsqrtf(d2);
    }
    __syncthreads();

    for (int i = tid; i < NF * EPR; i += TBE) {
        int e = i & (EPR - 1), f = i >> 7;
        int ec = min(e0 + e, EI - 1);
        shL [f * EPR + e] = g_lig[ec * NF + f];
        shRn[f * EPR + e] = g_node[shRi[e] * NF + f];
    }

    float h[4][KC];
    {
        int kb = warp * KC;
#pragma unroll 1
        for (int s = 0; s < 4; s++) {
            float aa[20];
            demb_compute(shD[lane + s * 32], aa);
#pragma unroll
            for (int j = 0; j < KC; j++) {
                float sm = 0.0f;
#pragma unroll
                for (int i = 0; i < 20; i++) sm += aa[i] * W0[i * 64 + kb + j];
                h[s][j] = siluN(sm) * 0.125f;
            }
        }
    }
    __syncthreads();

    float acc[4][8];
#pragma unroll
    for (int s = 0; s < 4; s++)
#pragma unroll
        for (int t = 0; t < 8; t++) acc[s][t] = 0.0f;
    const float* Wk = W1 + warp * KC * 2560;

    // scalar x scalar -> 8x0e : w1[u][v][o] at (u*16+v)*8
#pragma unroll 1
    for (int u = 0; u < 16; u++) {
        float lu[4];
#pragma unroll
        for (int s = 0; s < 4; s++) lu[s] = shL[u * EPR + lane + s * 32];
#pragma unroll 1
        for (int v = 0; v < 16; v++) {
            float cf[4];
#pragma unroll
            for (int s = 0; s < 4; s++) cf[s] = lu[s] * shRn[v * EPR + lane + s * 32];
            const float* base = Wk + (u * 16 + v) * 8;
#pragma unroll
            for (int j = 0; j < KC; j++) {
                float p[4];
#pragma unroll
                for (int s = 0; s < 4; s++) p[s] = cf[s] * h[s][j];
                const float4* bp = reinterpret_cast<const float4*>(base + j * 2560);
                float4 q0 = __ldg(bp), q1 = __ldg(bp + 1);
#pragma unroll
                for (int s = 0; s < 4; s++) {
                    acc[s][0] += p[s] * q0.x; acc[s][1] += p[s] * q0.y;
                    acc[s][2] += p[s] * q0.z; acc[s][3] += p[s] * q0.w;
                    acc[s][4] += p[s] * q1.x; acc[s][5] += p[s] * q1.y;
                    acc[s][6] += p[s] * q1.z; acc[s][7] += p[s] * q1.w;
                }
            }
        }
    }

    // vector x vector -> 8x0e : w2 at 2048 + (u*8+v)*8, coef (lv.rv)/sqrt3
#pragma unroll 1
    for (int u = 0; u < 8; u++) {
        float la0[4], la1[4], la2[4];
#pragma unroll
        for (int s = 0; s < 4; s++) {
            int idx = lane + s * 32;
            la0[s] = shL[(16 + u * 3) * EPR + idx];
            la1[s] = shL[(17 + u * 3) * EPR + idx];
            la2[s] = shL[(18 + u * 3) * EPR + idx];
        }
#pragma unroll 1
        for (int v = 0; v < 8; v++) {
            float cf[4];
#pragma unroll
            for (int s = 0; s < 4; s++) {
                int idx = lane + s * 32;
                cf[s] = (la0[s] * shRn[(16 + v * 3) * EPR + idx] +
                         la1[s] * shRn[(17 + v * 3) * EPR + idx] +
                         la2[s] * shRn[(18 + v * 3) * EPR + idx]) * INVS3;
            }
            const float* base = Wk + 2048 + (u * 8 + v) * 8;
#pragma unroll
            for (int j = 0; j < KC; j++) {
                float p[4];
#pragma unroll
                for (int s = 0; s < 4; s++) p[s] = cf[s] * h[s][j];
                const float4* bp = reinterpret_cast<const float4*>(base + j * 2560);
                float4 q0 = __ldg(bp), q1 = __ldg(bp + 1);
#pragma unroll
                for (int s = 0; s < 4; s++) {
                    acc[s][0] += p[s] * q0.x; acc[s][1] += p[s] * q0.y;
                    acc[s][2] += p[s] * q0.z; acc[s][3] += p[s] * q0.w;
                    acc[s][4] += p[s] * q1.x; acc[s][5] += p[s] * q1.y;
                    acc[s][6] += p[s] * q1.z; acc[s][7] += p[s] * q1.w;
                }
            }
        }
    }

    // reduce this warp's partials into (pre-zeroed) output
#pragma unroll
    for (int s = 0; s < 4; s++) {
        int e = e0 + lane + s * 32;
        if (e < EI) {
#pragma unroll
            for (int t = 0; t < 8; t++)
                atomicAdd(&out[e * 8 + t], PWREC * acc[s][t]);
        }
    }
}

// ---------------------------------------------------------------------------
// host launcher (graph-capturable: kernel launches only)
// ---------------------------------------------------------------------------
extern "C" void kernel_launch(void* const* d_in, const int* in_sizes, int n_in,
                              void* d_out, int out_size) {
    (void)n_in; (void)out_size;
    const float* x       = (const float*)d_in[0];
    const float* pos     = (const float*)d_in[1];
    const int*   eidx    = (const int*)  d_in[2];
    const float* eattr   = (const float*)d_in[3];
    const int*   iidx    = (const int*)  d_in[4];
    const float* emb_w0  = (const float*)d_in[5];
    const float* emb_w1  = (const float*)d_in[6];
    const float* imp0    = (const float*)d_in[7];
    const float* msg0_w0 = (const float*)d_in[8];
    const float* msg0_w1 = (const float*)d_in[9];
    const float* upd0_w0 = (const float*)d_in[10];
    const float* upd0_w1 = (const float*)d_in[11];
    const float* imp1    = (const float*)d_in[12];
    const float* msg1_w0 = (const float*)d_in[13];
    const float* msg1_w1 = (const float*)d_in[14];
    const float* upd1_w0 = (const float*)d_in[15];
    const float* upd1_w1 = (const float*)d_in[16];
    const float* lig_w0  = (const float*)d_in[17];
    const float* lig_w1  = (const float*)d_in[18];
    const float* rec_w0  = (const float*)d_in[19];
    const float* rec_w1  = (const float*)d_in[20];

    int N  = in_sizes[1] / 3;
    int A  = in_sizes[0] / N;
    int E  = in_sizes[2] / 2;
    int B  = in_sizes[3] / E;
    int EI = in_sizes[4] / 2;
    const int* src  = eidx;
    const int* dst  = eidx + E;
    const int* recI = iidx;
    const int* ligI = iidx + EI;
    float degf = (float)E / (float)N;

    int gn = (N + 127) / 128;
    int ge = (E + EPB - 1) / EPB;
    int gi = (EI + EPB - 1) / EPB;
    int gr = (EI + EPR - 1) / EPR;

    k_embed<<<gn, 128>>>(x, N, A, emb_w0, emb_w1);      // also zeroes g_msgs

    k_msg<<<ge, TBE>>>(pos, src, dst, eattr, E, B, msg0_w0, msg0_w1);
    k_update<<<gn, 128>>>(N, imp0, degf, upd0_w0, upd0_w1, 1.0f);  // re-zeroes g_msgs

    k_msg<<<ge, TBE>>>(pos, src, dst, eattr, E, B, msg1_w0, msg1_w1);
    k_update<<<gn, 128>>>(N, imp1, degf, upd1_w0, upd1_w1, 0.5f);

    k_lig<<<gi, TBE>>>(pos, recI, ligI, EI, lig_w0, lig_w1, (float*)d_out);  // zeroes d_out
    k_rec<<<gr, TBE>>>(pos, recI, ligI, EI, rec_w0, rec_w1, (float*)d_out);
}